// round 2
// baseline (speedup 1.0000x reference)
#include <cuda_runtime.h>
#include <math.h>

#define BB 8
#define VV 4096
#define LL 1024
#define DD 512
#define HH 8
#define HDIM 64

// ---------------- scratch (device globals; no allocations allowed) ----------
__device__ float g_params[BB * 2 * DD];          // adaLN params (8,1024)
__device__ float g_h[BB * VV * DD];              // modulated x (8,4096,512)
__device__ float g_ctxn[BB * LL * DD];           // normed context (8,1024,512)
__device__ float g_q[BB * VV * DD];              // q (8,4096,512)
__device__ float g_kv[BB * LL * 2 * DD];         // kv (8,1024,1024)
__device__ float g_ao[BB * VV * DD];             // attention out (8,4096,512)

// ---------------- 1. silu(cond) @ W_ada + b_ada -----------------------------
__global__ void __launch_bounds__(256) ada_kernel(const float* __restrict__ cond,
                                                  const float* __restrict__ W,
                                                  const float* __restrict__ bias) {
    __shared__ float sc[DD];
    const int b = blockIdx.x;
    for (int i = threadIdx.x; i < DD; i += 256) {
        float c = cond[b * DD + i];
        sc[i] = c / (1.f + __expf(-c));
    }
    __syncthreads();
    for (int j = threadIdx.x; j < 2 * DD; j += 256) {
        float acc = bias[j];
        #pragma unroll 8
        for (int d = 0; d < DD; d++) acc += sc[d] * W[d * 2 * DD + j];
        g_params[b * 2 * DD + j] = acc;
    }
}

// ---------------- 2. LN(x) * (1+scale) + shift  ->  g_h ----------------------
__global__ void __launch_bounds__(128) ln_x_kernel(const float* __restrict__ x) {
    const int row = blockIdx.x;            // b*V + v
    const int b = row >> 12;               // V = 4096
    const float* xr = x + (size_t)row * DD;
    float4 v = ((const float4*)xr)[threadIdx.x];
    float s = v.x + v.y + v.z + v.w;
    float sq = v.x * v.x + v.y * v.y + v.z * v.z + v.w * v.w;
    #pragma unroll
    for (int o = 16; o; o >>= 1) {
        s += __shfl_xor_sync(0xffffffffu, s, o);
        sq += __shfl_xor_sync(0xffffffffu, sq, o);
    }
    __shared__ float ss[4], ssq[4];
    const int w = threadIdx.x >> 5;
    if ((threadIdx.x & 31) == 0) { ss[w] = s; ssq[w] = sq; }
    __syncthreads();
    s = ss[0] + ss[1] + ss[2] + ss[3];
    sq = ssq[0] + ssq[1] + ssq[2] + ssq[3];
    const float mu = s * (1.f / DD);
    const float rstd = rsqrtf(sq * (1.f / DD) - mu * mu + 1e-5f);
    const int d0 = threadIdx.x * 4;
    const float* pr = g_params + b * 2 * DD;
    float4 o;
    o.x = (v.x - mu) * rstd * (1.f + pr[d0 + 0]) + pr[DD + d0 + 0];
    o.y = (v.y - mu) * rstd * (1.f + pr[d0 + 1]) + pr[DD + d0 + 1];
    o.z = (v.z - mu) * rstd * (1.f + pr[d0 + 2]) + pr[DD + d0 + 2];
    o.w = (v.w - mu) * rstd * (1.f + pr[d0 + 3]) + pr[DD + d0 + 3];
    ((float4*)(g_h + (size_t)row * DD))[threadIdx.x] = o;
}

// ---------------- 3. LN(context) * g + b  ->  g_ctxn -------------------------
__global__ void __launch_bounds__(128) ln_ctx_kernel(const float* __restrict__ c,
                                                     const float* __restrict__ g,
                                                     const float* __restrict__ bvec) {
    const int row = blockIdx.x;            // b*L + l
    const float* xr = c + (size_t)row * DD;
    float4 v = ((const float4*)xr)[threadIdx.x];
    float s = v.x + v.y + v.z + v.w;
    float sq = v.x * v.x + v.y * v.y + v.z * v.z + v.w * v.w;
    #pragma unroll
    for (int o = 16; o; o >>= 1) {
        s += __shfl_xor_sync(0xffffffffu, s, o);
        sq += __shfl_xor_sync(0xffffffffu, sq, o);
    }
    __shared__ float ss[4], ssq[4];
    const int w = threadIdx.x >> 5;
    if ((threadIdx.x & 31) == 0) { ss[w] = s; ssq[w] = sq; }
    __syncthreads();
    s = ss[0] + ss[1] + ss[2] + ss[3];
    sq = ssq[0] + ssq[1] + ssq[2] + ssq[3];
    const float mu = s * (1.f / DD);
    const float rstd = rsqrtf(sq * (1.f / DD) - mu * mu + 1e-5f);
    const int d0 = threadIdx.x * 4;
    float4 o;
    o.x = (v.x - mu) * rstd * g[d0 + 0] + bvec[d0 + 0];
    o.y = (v.y - mu) * rstd * g[d0 + 1] + bvec[d0 + 1];
    o.z = (v.z - mu) * rstd * g[d0 + 2] + bvec[d0 + 2];
    o.w = (v.w - mu) * rstd * g[d0 + 3] + bvec[d0 + 3];
    ((float4*)(g_ctxn + (size_t)row * DD))[threadIdx.x] = o;
}

// ---------------- generic fp32 tiled GEMM (64x64x16, 4x4/thread) ------------
template <bool BIAS, bool RES>
__global__ void __launch_bounds__(256) gemm64_kernel(
    const float* __restrict__ A, const float* __restrict__ Bm,
    const float* __restrict__ bias, const float* __restrict__ res,
    float* __restrict__ C, int M, int N, int K) {
    constexpr int BK = 16;
    __shared__ float As[BK][64];   // transposed: As[k][m]
    __shared__ float Bs[BK][64];   // natural:    Bs[k][n]
    const int tid = threadIdx.x;
    const int tx = tid & 15, ty = tid >> 4;
    const int m0 = blockIdx.y * 64, n0 = blockIdx.x * 64;
    const int ar = tid >> 2, ak = (tid & 3) * 4;
    const int br = tid >> 4, bc = (tid & 15) * 4;
    float acc[4][4] = {};
    const float* Aptr = A + (size_t)(m0 + ar) * K + ak;
    const float* Bptr = Bm + (size_t)br * N + n0 + bc;
    for (int k0 = 0; k0 < K; k0 += BK) {
        float4 a4 = *(const float4*)(Aptr + k0);
        float4 b4 = *(const float4*)(Bptr + (size_t)k0 * N);
        As[ak + 0][ar] = a4.x; As[ak + 1][ar] = a4.y;
        As[ak + 2][ar] = a4.z; As[ak + 3][ar] = a4.w;
        *(float4*)&Bs[br][bc] = b4;
        __syncthreads();
        #pragma unroll
        for (int k = 0; k < BK; k++) {
            float4 ra = *(float4*)&As[k][ty * 4];
            float4 rb = *(float4*)&Bs[k][tx * 4];
            acc[0][0] += ra.x * rb.x; acc[0][1] += ra.x * rb.y;
            acc[0][2] += ra.x * rb.z; acc[0][3] += ra.x * rb.w;
            acc[1][0] += ra.y * rb.x; acc[1][1] += ra.y * rb.y;
            acc[1][2] += ra.y * rb.z; acc[1][3] += ra.y * rb.w;
            acc[2][0] += ra.z * rb.x; acc[2][1] += ra.z * rb.y;
            acc[2][2] += ra.z * rb.z; acc[2][3] += ra.z * rb.w;
            acc[3][0] += ra.w * rb.x; acc[3][1] += ra.w * rb.y;
            acc[3][2] += ra.w * rb.z; acc[3][3] += ra.w * rb.w;
        }
        __syncthreads();
    }
    const int col = n0 + tx * 4;
    #pragma unroll
    for (int i = 0; i < 4; i++) {
        const int row = m0 + ty * 4 + i;
        float4 o;
        o.x = acc[i][0]; o.y = acc[i][1]; o.z = acc[i][2]; o.w = acc[i][3];
        if (BIAS) {
            o.x += bias[col]; o.y += bias[col + 1];
            o.z += bias[col + 2]; o.w += bias[col + 3];
        }
        if (RES) {
            float4 r4 = *(const float4*)&res[(size_t)row * N + col];
            o.x += r4.x; o.y += r4.y; o.z += r4.z; o.w += r4.w;
        }
        *(float4*)&C[(size_t)row * N + col] = o;
    }
}

// ---------------- flash attention (BQ=64, BL=64, HD=64) ----------------------
#define SP 68
#define ATTN_SMEM (4 * HDIM * SP * 4 + 256)
__global__ void __launch_bounds__(256) attn_kernel(const int* __restrict__ cmask) {
    extern __shared__ float sm[];
    float* QsT = sm;                   // [d][r] stride SP
    float* KsT = sm + HDIM * SP;       // [d][c]
    float* Vs  = sm + 2 * HDIM * SP;   // [l][d]
    float* Ps  = sm + 3 * HDIM * SP;   // [r][c]
    int* ms = (int*)(sm + 4 * HDIM * SP);

    const int bh = blockIdx.y, b = bh >> 3, h = bh & 7;
    const int q0 = blockIdx.x * 64;
    const int tid = threadIdx.x, tx = tid & 15, ty = tid >> 4;

    const float* qp = g_q + (size_t)(b * VV + q0) * DD + h * HDIM;
    #pragma unroll
    for (int it = 0; it < 4; it++) {
        int f = tid + it * 256;
        int r = f >> 4, d0 = (f & 15) * 4;
        float4 a = *(const float4*)(qp + (size_t)r * DD + d0);
        QsT[(d0 + 0) * SP + r] = a.x; QsT[(d0 + 1) * SP + r] = a.y;
        QsT[(d0 + 2) * SP + r] = a.z; QsT[(d0 + 3) * SP + r] = a.w;
    }

    float mrow[4], lrow[4], o[4][4];
    #pragma unroll
    for (int i = 0; i < 4; i++) {
        mrow[i] = -1e30f; lrow[i] = 0.f;
        #pragma unroll
        for (int j = 0; j < 4; j++) o[i][j] = 0.f;
    }

    for (int l0 = 0; l0 < LL; l0 += 64) {
        __syncthreads();
        const float* kp = g_kv + (size_t)(b * LL + l0) * (2 * DD) + h * HDIM;
        const float* vp = kp + DD;
        #pragma unroll
        for (int it = 0; it < 4; it++) {
            int f = tid + it * 256;
            int c = f >> 4, d0 = (f & 15) * 4;
            float4 a = *(const float4*)(kp + (size_t)c * (2 * DD) + d0);
            KsT[(d0 + 0) * SP + c] = a.x; KsT[(d0 + 1) * SP + c] = a.y;
            KsT[(d0 + 2) * SP + c] = a.z; KsT[(d0 + 3) * SP + c] = a.w;
            float4 vv = *(const float4*)(vp + (size_t)c * (2 * DD) + d0);
            *(float4*)&Vs[c * SP + d0] = vv;
        }
        // bool mask is uploaded as int32 (4-byte elements)
        if (tid < 64) ms[tid] = cmask[(size_t)b * LL + l0 + tid];
        __syncthreads();

        float s[4][4] = {};
        #pragma unroll 8
        for (int d = 0; d < HDIM; d++) {
            float4 ra = *(float4*)&QsT[d * SP + ty * 4];
            float4 rb = *(float4*)&KsT[d * SP + tx * 4];
            s[0][0] += ra.x * rb.x; s[0][1] += ra.x * rb.y;
            s[0][2] += ra.x * rb.z; s[0][3] += ra.x * rb.w;
            s[1][0] += ra.y * rb.x; s[1][1] += ra.y * rb.y;
            s[1][2] += ra.y * rb.z; s[1][3] += ra.y * rb.w;
            s[2][0] += ra.z * rb.x; s[2][1] += ra.z * rb.y;
            s[2][2] += ra.z * rb.z; s[2][3] += ra.z * rb.w;
            s[3][0] += ra.w * rb.x; s[3][1] += ra.w * rb.y;
            s[3][2] += ra.w * rb.z; s[3][3] += ra.w * rb.w;
        }
        // scale + mask (masked -> -1e30 so fully-masked rows go uniform like jax)
        bool valid[4];
        #pragma unroll
        for (int j = 0; j < 4; j++) valid[j] = (ms[tx * 4 + j] != 0);
        #pragma unroll
        for (int i = 0; i < 4; i++)
            #pragma unroll
            for (int j = 0; j < 4; j++)
                s[i][j] = valid[j] ? s[i][j] * 0.125f : -1e30f;

        #pragma unroll
        for (int i = 0; i < 4; i++) {
            float rm = fmaxf(fmaxf(s[i][0], s[i][1]), fmaxf(s[i][2], s[i][3]));
            #pragma unroll
            for (int off = 8; off; off >>= 1)
                rm = fmaxf(rm, __shfl_xor_sync(0xffffffffu, rm, off));
            float mnew = fmaxf(mrow[i], rm);
            float corr = __expf(mrow[i] - mnew);
            mrow[i] = mnew;
            float rs = 0.f;
            #pragma unroll
            for (int j = 0; j < 4; j++) {
                s[i][j] = __expf(s[i][j] - mnew);
                rs += s[i][j];
            }
            #pragma unroll
            for (int off = 8; off; off >>= 1)
                rs += __shfl_xor_sync(0xffffffffu, rs, off);
            lrow[i] = lrow[i] * corr + rs;
            #pragma unroll
            for (int j = 0; j < 4; j++) o[i][j] *= corr;
            // store P row (natural layout, float4 -> conflict-free)
            float4 pv; pv.x = s[i][0]; pv.y = s[i][1]; pv.z = s[i][2]; pv.w = s[i][3];
            *(float4*)&Ps[(ty * 4 + i) * SP + tx * 4] = pv;
        }
        __syncthreads();

        // O += P @ V
        #pragma unroll 8
        for (int l = 0; l < 64; l++) {
            float p0 = Ps[(ty * 4 + 0) * SP + l];
            float p1 = Ps[(ty * 4 + 1) * SP + l];
            float p2 = Ps[(ty * 4 + 2) * SP + l];
            float p3 = Ps[(ty * 4 + 3) * SP + l];
            float4 rv = *(float4*)&Vs[l * SP + tx * 4];
            o[0][0] += p0 * rv.x; o[0][1] += p0 * rv.y; o[0][2] += p0 * rv.z; o[0][3] += p0 * rv.w;
            o[1][0] += p1 * rv.x; o[1][1] += p1 * rv.y; o[1][2] += p1 * rv.z; o[1][3] += p1 * rv.w;
            o[2][0] += p2 * rv.x; o[2][1] += p2 * rv.y; o[2][2] += p2 * rv.z; o[2][3] += p2 * rv.w;
            o[3][0] += p3 * rv.x; o[3][1] += p3 * rv.y; o[3][2] += p3 * rv.z; o[3][3] += p3 * rv.w;
        }
    }

    float* op = g_ao + (size_t)(b * VV + q0) * DD + h * HDIM;
    #pragma unroll
    for (int i = 0; i < 4; i++) {
        float inv = 1.f / lrow[i];
        float4 ov;
        ov.x = o[i][0] * inv; ov.y = o[i][1] * inv;
        ov.z = o[i][2] * inv; ov.w = o[i][3] * inv;
        *(float4*)(op + (size_t)(ty * 4 + i) * DD + tx * 4) = ov;
    }
}

// ---------------- launch ------------------------------------------------------
extern "C" void kernel_launch(void* const* d_in, const int* in_sizes, int n_in,
                              void* d_out, int out_size) {
    const float* x        = (const float*)d_in[0];
    const float* context  = (const float*)d_in[1];
    const float* cond     = (const float*)d_in[2];
    const int*   cmask    = (const int*)d_in[3];
    const float* W_ada    = (const float*)d_in[4];
    const float* b_ada    = (const float*)d_in[5];
    const float* g_ctx    = (const float*)d_in[6];
    const float* b_ctx    = (const float*)d_in[7];
    const float* Wq       = (const float*)d_in[8];
    const float* Wkv      = (const float*)d_in[9];
    const float* Wp       = (const float*)d_in[10];
    const float* bp       = (const float*)d_in[11];
    float* out = (float*)d_out;

    float *ph, *pctxn, *pq, *pkv, *pao;
    cudaGetSymbolAddress((void**)&ph, g_h);
    cudaGetSymbolAddress((void**)&pctxn, g_ctxn);
    cudaGetSymbolAddress((void**)&pq, g_q);
    cudaGetSymbolAddress((void**)&pkv, g_kv);
    cudaGetSymbolAddress((void**)&pao, g_ao);

    cudaFuncSetAttribute(attn_kernel, cudaFuncAttributeMaxDynamicSharedMemorySize,
                         ATTN_SMEM);

    ada_kernel<<<BB, 256>>>(cond, W_ada, b_ada);
    ln_x_kernel<<<BB * VV, 128>>>(x);
    ln_ctx_kernel<<<BB * LL, 128>>>(context, g_ctx, b_ctx);

    // q = h @ Wq : (32768 x 512) * (512 x 512)
    gemm64_kernel<false, false><<<dim3(DD / 64, BB * VV / 64), 256>>>(
        ph, Wq, nullptr, nullptr, pq, BB * VV, DD, DD);
    // kv = ctxn @ Wkv : (8192 x 512) * (512 x 1024)
    gemm64_kernel<false, false><<<dim3(2 * DD / 64, BB * LL / 64), 256>>>(
        pctxn, Wkv, nullptr, nullptr, pkv, BB * LL, 2 * DD, DD);

    attn_kernel<<<dim3(VV / 64, BB * HH), 256, ATTN_SMEM>>>(cmask);

    // out = ao @ Wp + bp + x
    gemm64_kernel<true, true><<<dim3(DD / 64, BB * VV / 64), 256>>>(
        pao, Wp, bp, x, out, BB * VV, DD, DD);
}

// round 5
// speedup vs baseline: 2.6357x; 2.6357x over previous
#include <cuda_runtime.h>
#include <cstdint>
#include <cstddef>

typedef unsigned short bf16;   // raw bf16 storage; no cuda_bf16.h needed

#define BB 8
#define VV 4096
#define LL 1024
#define DD 512
#define HH 8
#define HDIM 64

// ---------------- scratch (device globals; no allocations allowed) ----------
__device__ float g_params[BB * 2 * DD];
__device__ bf16  g_h[BB * VV * DD];
__device__ bf16  g_ctxn[BB * LL * DD];
__device__ bf16  g_q[BB * VV * DD];
__device__ bf16  g_kv[BB * LL * 2 * DD];
__device__ bf16  g_ao[BB * VV * DD];
__device__ bf16  g_wq[DD * DD];
__device__ bf16  g_wkv[DD * 2 * DD];
__device__ bf16  g_wp[DD * DD];

// ---------------- helpers ----------------------------------------------------
__device__ __forceinline__ unsigned pack2(float a, float b) {
    unsigned r;
    asm("cvt.rn.bf16x2.f32 %0, %1, %2;" : "=r"(r) : "f"(b), "f"(a));
    return r;
}
__device__ __forceinline__ uint32_t sptr(const void* p) {
    return (uint32_t)__cvta_generic_to_shared(p);
}
__device__ __forceinline__ void ldm_x4(uint32_t* r, uint32_t a) {
    asm volatile("ldmatrix.sync.aligned.m8n8.x4.shared.b16 {%0,%1,%2,%3}, [%4];"
                 : "=r"(r[0]), "=r"(r[1]), "=r"(r[2]), "=r"(r[3]) : "r"(a));
}
__device__ __forceinline__ void ldm_x4t(uint32_t* r, uint32_t a) {
    asm volatile("ldmatrix.sync.aligned.m8n8.x4.trans.shared.b16 {%0,%1,%2,%3}, [%4];"
                 : "=r"(r[0]), "=r"(r[1]), "=r"(r[2]), "=r"(r[3]) : "r"(a));
}
__device__ __forceinline__ void mma16816(float* d, const uint32_t* a,
                                         const uint32_t* b) {
    asm volatile(
        "mma.sync.aligned.m16n8k16.row.col.f32.bf16.bf16.f32 "
        "{%0,%1,%2,%3},{%4,%5,%6,%7},{%8,%9},{%0,%1,%2,%3};"
        : "+f"(d[0]), "+f"(d[1]), "+f"(d[2]), "+f"(d[3])
        : "r"(a[0]), "r"(a[1]), "r"(a[2]), "r"(a[3]), "r"(b[0]), "r"(b[1]));
}
// fast e^x for x <= 0 (FFMA/ALU only; avoids MUFU bottleneck)
__device__ __forceinline__ float fexp(float x) {
    float t = fmaxf(x * 1.44269504f, -126.f);
    int ti = __float2int_rn(t);
    float f = t - (float)ti;
    float p = 0.00961813f;
    p = p * f + 0.0555041f;
    p = p * f + 0.240227f;
    p = p * f + 0.693147f;
    p = p * f + 1.0f;
    return __int_as_float((ti + 127) << 23) * p;
}

// ---------------- weight fp32 -> bf16 ----------------------------------------
__global__ void __launch_bounds__(256) cvtw_kernel(const float* __restrict__ src,
                                                   bf16* __restrict__ dst, int n) {
    int i = (blockIdx.x * 256 + threadIdx.x) * 4;
    if (i < n) {
        float4 v = *(const float4*)(src + i);
        *(uint2*)(dst + i) = make_uint2(pack2(v.x, v.y), pack2(v.z, v.w));
    }
}

// ---------------- 1. silu(cond) @ W_ada + b_ada ------------------------------
__global__ void __launch_bounds__(256) ada_kernel(const float* __restrict__ cond,
                                                  const float* __restrict__ W,
                                                  const float* __restrict__ bias) {
    __shared__ float sc[DD];
    const int b = blockIdx.x;
    for (int i = threadIdx.x; i < DD; i += 256) {
        float c = cond[b * DD + i];
        sc[i] = c / (1.f + __expf(-c));
    }
    __syncthreads();
    for (int j = threadIdx.x; j < 2 * DD; j += 256) {
        float acc = bias[j];
        #pragma unroll 8
        for (int d = 0; d < DD; d++) acc += sc[d] * W[d * 2 * DD + j];
        g_params[b * 2 * DD + j] = acc;
    }
}

// ---------------- 2. LN(x)*(1+scale)+shift -> g_h (bf16) ---------------------
__global__ void __launch_bounds__(128) ln_x_kernel(const float* __restrict__ x) {
    const int row = blockIdx.x;
    const int b = row >> 12;
    const float* xr = x + (size_t)row * DD;
    float4 v = ((const float4*)xr)[threadIdx.x];
    float s = v.x + v.y + v.z + v.w;
    float sq = v.x * v.x + v.y * v.y + v.z * v.z + v.w * v.w;
    #pragma unroll
    for (int o = 16; o; o >>= 1) {
        s += __shfl_xor_sync(0xffffffffu, s, o);
        sq += __shfl_xor_sync(0xffffffffu, sq, o);
    }
    __shared__ float ss[4];
    __shared__ float ssq[4];
    const int w = threadIdx.x >> 5;
    if ((threadIdx.x & 31) == 0) { ss[w] = s; ssq[w] = sq; }
    __syncthreads();
    s = ss[0] + ss[1] + ss[2] + ss[3];
    sq = ssq[0] + ssq[1] + ssq[2] + ssq[3];
    const float mu = s * (1.f / DD);
    const float rstd = rsqrtf(sq * (1.f / DD) - mu * mu + 1e-5f);
    const int d0 = threadIdx.x * 4;
    const float* pr = g_params + b * 2 * DD;
    float o0 = (v.x - mu) * rstd * (1.f + pr[d0 + 0]) + pr[DD + d0 + 0];
    float o1 = (v.y - mu) * rstd * (1.f + pr[d0 + 1]) + pr[DD + d0 + 1];
    float o2 = (v.z - mu) * rstd * (1.f + pr[d0 + 2]) + pr[DD + d0 + 2];
    float o3 = (v.w - mu) * rstd * (1.f + pr[d0 + 3]) + pr[DD + d0 + 3];
    ((uint2*)(g_h + (size_t)row * DD))[threadIdx.x] =
        make_uint2(pack2(o0, o1), pack2(o2, o3));
}

// ---------------- 3. LN(context)*g+b -> g_ctxn (bf16) ------------------------
__global__ void __launch_bounds__(128) ln_ctx_kernel(const float* __restrict__ c,
                                                     const float* __restrict__ gam,
                                                     const float* __restrict__ bvec) {
    const int row = blockIdx.x;
    const float* xr = c + (size_t)row * DD;
    float4 v = ((const float4*)xr)[threadIdx.x];
    float s = v.x + v.y + v.z + v.w;
    float sq = v.x * v.x + v.y * v.y + v.z * v.z + v.w * v.w;
    #pragma unroll
    for (int o = 16; o; o >>= 1) {
        s += __shfl_xor_sync(0xffffffffu, s, o);
        sq += __shfl_xor_sync(0xffffffffu, sq, o);
    }
    __shared__ float ss[4];
    __shared__ float ssq[4];
    const int w = threadIdx.x >> 5;
    if ((threadIdx.x & 31) == 0) { ss[w] = s; ssq[w] = sq; }
    __syncthreads();
    s = ss[0] + ss[1] + ss[2] + ss[3];
    sq = ssq[0] + ssq[1] + ssq[2] + ssq[3];
    const float mu = s * (1.f / DD);
    const float rstd = rsqrtf(sq * (1.f / DD) - mu * mu + 1e-5f);
    const int d0 = threadIdx.x * 4;
    float o0 = (v.x - mu) * rstd * gam[d0 + 0] + bvec[d0 + 0];
    float o1 = (v.y - mu) * rstd * gam[d0 + 1] + bvec[d0 + 1];
    float o2 = (v.z - mu) * rstd * gam[d0 + 2] + bvec[d0 + 2];
    float o3 = (v.w - mu) * rstd * gam[d0 + 3] + bvec[d0 + 3];
    ((uint2*)(g_ctxn + (size_t)row * DD))[threadIdx.x] =
        make_uint2(pack2(o0, o1), pack2(o2, o3));
}

// ---------------- bf16 tensor-core GEMM: C[M,N] = A[M,K] @ B[K,N] ------------
// CTA 128x128, BK=64, 8 warps (2x4), warp tile 64x32.
template <int OUT_BF16, int BIAS, int RES>
__global__ void __launch_bounds__(256) gemm_mma_kernel(
    const bf16* __restrict__ A, const bf16* __restrict__ B,
    const float* __restrict__ bias, const float* __restrict__ res,
    void* __restrict__ Cv, int M, int N, int K) {
    __shared__ bf16 As[128][72];
    __shared__ bf16 Bs[64][136];
    const int tid = threadIdx.x;
    const int lane = tid & 31;
    const int warp = tid >> 5;
    const int wm = warp >> 2;
    const int wn = warp & 3;
    const int m0 = blockIdx.y * 128;
    const int n0 = blockIdx.x * 128;
    float acc[4][4][4] = {};

    for (int k0 = 0; k0 < K; k0 += 64) {
        #pragma unroll
        for (int i = 0; i < 4; i++) {
            int c = tid + i * 256;
            int r = c >> 3;
            int col = (c & 7) * 8;
            *(uint4*)&As[r][col] = *(const uint4*)(A + (size_t)(m0 + r) * K + k0 + col);
        }
        #pragma unroll
        for (int i = 0; i < 4; i++) {
            int c = tid + i * 256;
            int r = c >> 4;
            int col = (c & 15) * 8;
            *(uint4*)&Bs[r][col] = *(const uint4*)(B + (size_t)(k0 + r) * N + n0 + col);
        }
        __syncthreads();
        #pragma unroll
        for (int ks = 0; ks < 4; ks++) {
            uint32_t af[4][4];
            #pragma unroll
            for (int mi = 0; mi < 4; mi++) {
                ldm_x4(af[mi], sptr(&As[wm * 64 + mi * 16 + (lane & 15)]
                                      [ks * 16 + (lane >> 4) * 8]));
            }
            uint32_t bq[2][4];
            #pragma unroll
            for (int nj = 0; nj < 2; nj++) {
                ldm_x4t(bq[nj], sptr(&Bs[ks * 16 + (lane & 15)]
                                       [wn * 32 + nj * 16 + (lane >> 4) * 8]));
            }
            #pragma unroll
            for (int mi = 0; mi < 4; mi++) {
                #pragma unroll
                for (int ni = 0; ni < 4; ni++) {
                    uint32_t bb[2];
                    bb[0] = bq[ni >> 1][(ni & 1) * 2];
                    bb[1] = bq[ni >> 1][(ni & 1) * 2 + 1];
                    mma16816(acc[mi][ni], af[mi], bb);
                }
            }
        }
        __syncthreads();
    }

    const int grp = lane >> 2;
    const int tig = lane & 3;
    #pragma unroll
    for (int mi = 0; mi < 4; mi++) {
        #pragma unroll
        for (int ni = 0; ni < 4; ni++) {
            const int row = m0 + wm * 64 + mi * 16 + grp;
            const int col = n0 + wn * 32 + ni * 8 + tig * 2;
            if (OUT_BF16) {
                bf16* C = (bf16*)Cv;
                *(unsigned*)&C[(size_t)row * N + col] =
                    pack2(acc[mi][ni][0], acc[mi][ni][1]);
                *(unsigned*)&C[(size_t)(row + 8) * N + col] =
                    pack2(acc[mi][ni][2], acc[mi][ni][3]);
            } else {
                float* C = (float*)Cv;
                float b0 = 0.f;
                float b1 = 0.f;
                if (BIAS) { b0 = bias[col]; b1 = bias[col + 1]; }
                float2 v0 = make_float2(acc[mi][ni][0] + b0, acc[mi][ni][1] + b1);
                float2 v1 = make_float2(acc[mi][ni][2] + b0, acc[mi][ni][3] + b1);
                if (RES) {
                    float2 r0 = *(const float2*)&res[(size_t)row * N + col];
                    float2 r1 = *(const float2*)&res[(size_t)(row + 8) * N + col];
                    v0.x += r0.x; v0.y += r0.y; v1.x += r1.x; v1.y += r1.y;
                }
                *(float2*)&C[(size_t)row * N + col] = v0;
                *(float2*)&C[(size_t)(row + 8) * N + col] = v1;
            }
        }
    }
}

// ---------------- flash attention, tensor cores ------------------------------
// CTA: one (b,h), 64 q rows; loop over L in chunks of 128. 8 warps.
#define ATTN_SMEM_BYTES 98560
__global__ void __launch_bounds__(256) attn_mma_kernel(const int* __restrict__ cmask) {
    extern __shared__ __align__(16) char sm_raw[];
    bf16* Qs = (bf16*)sm_raw;              // [64][72]
    bf16* Ks = Qs + 64 * 72;               // [128][72]
    bf16* Vs = Ks + 128 * 72;              // [128][72]
    bf16* Ps = Vs + 128 * 72;              // [64][136]
    float* Ss = (float*)(Ps + 64 * 136);   // [64][132]
    float* smax = Ss + 64 * 132;
    float* ssum = smax + 64;
    float* scorr = ssum + 64;
    int* smask = (int*)(scorr + 64);       // [128]

    const int bh = blockIdx.y;
    const int b = bh >> 3;
    const int h = bh & 7;
    const int q0 = blockIdx.x * 64;
    const int tid = threadIdx.x;
    const int lane = tid & 31;
    const int warp = tid >> 5;
    const int grp = lane >> 2;
    const int tig = lane & 3;
    const int wm = warp >> 2;
    const int wn = warp & 3;

    const bf16* qp = g_q + (size_t)(b * VV + q0) * DD + h * HDIM;
    #pragma unroll
    for (int i = 0; i < 2; i++) {
        int c = tid + i * 256;
        int r = c >> 3;
        int col = (c & 7) * 8;
        *(uint4*)&Qs[r * 72 + col] = *(const uint4*)(qp + (size_t)r * DD + col);
    }
    if (tid < 64) { smax[tid] = -1e30f; ssum[tid] = 0.f; }

    float opv[2][2][4] = {};

    for (int l0 = 0; l0 < LL; l0 += 128) {
        __syncthreads();
        const bf16* kp = g_kv + (size_t)(b * LL + l0) * (2 * DD) + h * HDIM;
        #pragma unroll
        for (int i = 0; i < 4; i++) {
            int c = tid + i * 256;
            int r = c >> 3;
            int col = (c & 7) * 8;
            *(uint4*)&Ks[r * 72 + col] =
                *(const uint4*)(kp + (size_t)r * (2 * DD) + col);
            *(uint4*)&Vs[r * 72 + col] =
                *(const uint4*)(kp + (size_t)r * (2 * DD) + DD + col);
        }
        if (tid < 128) smask[tid] = cmask[(size_t)b * LL + l0 + tid];
        __syncthreads();

        // ---- S = Q @ K^T : warp handles cols [warp*16, warp*16+16) ----
        float sacc[4][2][4] = {};
        #pragma unroll
        for (int ks = 0; ks < 4; ks++) {
            uint32_t af[4][4];
            #pragma unroll
            for (int mi = 0; mi < 4; mi++) {
                ldm_x4(af[mi], sptr(&Qs[(mi * 16 + (lane & 15)) * 72 +
                                        ks * 16 + (lane >> 4) * 8]));
            }
            uint32_t kf[4];
            ldm_x4(kf, sptr(&Ks[(warp * 16 + (lane & 15)) * 72 +
                                ks * 16 + (lane >> 4) * 8]));
            uint32_t b0[2];
            uint32_t b1[2];
            b0[0] = kf[0]; b0[1] = kf[2];
            b1[0] = kf[1]; b1[1] = kf[3];
            #pragma unroll
            for (int mi = 0; mi < 4; mi++) {
                mma16816(sacc[mi][0], af[mi], b0);
                mma16816(sacc[mi][1], af[mi], b1);
            }
        }
        #pragma unroll
        for (int mi = 0; mi < 4; mi++) {
            #pragma unroll
            for (int ni = 0; ni < 2; ni++) {
                int r = mi * 16 + grp;
                int cc = warp * 16 + ni * 8 + tig * 2;
                *(float2*)&Ss[r * 132 + cc] =
                    make_float2(sacc[mi][ni][0], sacc[mi][ni][1]);
                *(float2*)&Ss[(r + 8) * 132 + cc] =
                    make_float2(sacc[mi][ni][2], sacc[mi][ni][3]);
            }
        }
        __syncthreads();

        // ---- softmax: 4 threads per row, 32 cols each ----
        {
            const int r = tid >> 2;
            const int p = tid & 3;
            const float* srow = Ss + r * 132 + p * 32;
            const int* mrow = smask + p * 32;
            float mx = -1e30f;
            #pragma unroll
            for (int j = 0; j < 32; j++) {
                float sv = mrow[j] ? srow[j] * 0.125f : -1e30f;
                mx = fmaxf(mx, sv);
            }
            mx = fmaxf(mx, __shfl_xor_sync(0xffffffffu, mx, 1));
            mx = fmaxf(mx, __shfl_xor_sync(0xffffffffu, mx, 2));
            float mold = smax[r];
            float mnew = fmaxf(mold, mx);
            float sum = 0.f;
            bf16* prow = Ps + r * 136 + p * 32;
            #pragma unroll
            for (int j = 0; j < 32; j += 2) {
                float sv0 = mrow[j] ? srow[j] * 0.125f : -1e30f;
                float sv1 = mrow[j + 1] ? srow[j + 1] * 0.125f : -1e30f;
                float e0 = fexp(sv0 - mnew);
                float e1 = fexp(sv1 - mnew);
                sum += e0 + e1;
                *(unsigned*)&prow[j] = pack2(e0, e1);
            }
            sum += __shfl_xor_sync(0xffffffffu, sum, 1);
            sum += __shfl_xor_sync(0xffffffffu, sum, 2);
            if (p == 0) {
                float corr = fexp(mold - mnew);
                smax[r] = mnew;
                ssum[r] = ssum[r] * corr + sum;
                scorr[r] = corr;
            }
        }
        __syncthreads();

        // ---- O = O*corr + P @ V : warp tile 32x16 ----
        #pragma unroll
        for (int mi = 0; mi < 2; mi++) {
            float c0 = scorr[wm * 32 + mi * 16 + grp];
            float c1 = scorr[wm * 32 + mi * 16 + 8 + grp];
            #pragma unroll
            for (int ni = 0; ni < 2; ni++) {
                opv[mi][ni][0] *= c0; opv[mi][ni][1] *= c0;
                opv[mi][ni][2] *= c1; opv[mi][ni][3] *= c1;
            }
        }
        #pragma unroll
        for (int ks = 0; ks < 8; ks++) {
            uint32_t af[2][4];
            #pragma unroll
            for (int mi = 0; mi < 2; mi++) {
                ldm_x4(af[mi], sptr(&Ps[(wm * 32 + mi * 16 + (lane & 15)) * 136 +
                                        ks * 16 + (lane >> 4) * 8]));
            }
            uint32_t vf[4];
            ldm_x4t(vf, sptr(&Vs[(ks * 16 + (lane & 15)) * 72 +
                                 wn * 16 + (lane >> 4) * 8]));
            uint32_t b0[2];
            uint32_t b1[2];
            b0[0] = vf[0]; b0[1] = vf[1];
            b1[0] = vf[2]; b1[1] = vf[3];
            #pragma unroll
            for (int mi = 0; mi < 2; mi++) {
                mma16816(opv[mi][0], af[mi], b0);
                mma16816(opv[mi][1], af[mi], b1);
            }
        }
    }
    __syncthreads();

    bf16* op = g_ao + (size_t)(b * VV + q0) * DD + h * HDIM;
    #pragma unroll
    for (int mi = 0; mi < 2; mi++) {
        int r0 = wm * 32 + mi * 16 + grp;
        float inv0 = 1.f / ssum[r0];
        float inv1 = 1.f / ssum[r0 + 8];
        #pragma unroll
        for (int ni = 0; ni < 2; ni++) {
            int cc = wn * 16 + ni * 8 + tig * 2;
            *(unsigned*)&op[(size_t)r0 * DD + cc] =
                pack2(opv[mi][ni][0] * inv0, opv[mi][ni][1] * inv0);
            *(unsigned*)&op[(size_t)(r0 + 8) * DD + cc] =
                pack2(opv[mi][ni][2] * inv1, opv[mi][ni][3] * inv1);
        }
    }
}

// ---------------- launch ------------------------------------------------------
extern "C" void kernel_launch(void* const* d_in, const int* in_sizes, int n_in,
                              void* d_out, int out_size) {
    const float* x       = (const float*)d_in[0];
    const float* context = (const float*)d_in[1];
    const float* cond    = (const float*)d_in[2];
    const int*   cmask   = (const int*)d_in[3];
    const float* W_ada   = (const float*)d_in[4];
    const float* b_ada   = (const float*)d_in[5];
    const float* g_ctx   = (const float*)d_in[6];
    const float* b_ctx   = (const float*)d_in[7];
    const float* Wq      = (const float*)d_in[8];
    const float* Wkv     = (const float*)d_in[9];
    const float* Wp      = (const float*)d_in[10];
    const float* bp      = (const float*)d_in[11];
    float* out = (float*)d_out;

    bf16* ph;
    bf16* pctxn;
    bf16* pq;
    bf16* pkv;
    bf16* pao;
    bf16* pwq;
    bf16* pwkv;
    bf16* pwp;
    cudaGetSymbolAddress((void**)&ph, g_h);
    cudaGetSymbolAddress((void**)&pctxn, g_ctxn);
    cudaGetSymbolAddress((void**)&pq, g_q);
    cudaGetSymbolAddress((void**)&pkv, g_kv);
    cudaGetSymbolAddress((void**)&pao, g_ao);
    cudaGetSymbolAddress((void**)&pwq, g_wq);
    cudaGetSymbolAddress((void**)&pwkv, g_wkv);
    cudaGetSymbolAddress((void**)&pwp, g_wp);

    cudaFuncSetAttribute(attn_mma_kernel,
                         cudaFuncAttributeMaxDynamicSharedMemorySize,
                         ATTN_SMEM_BYTES);

    int nq = DD * DD;
    int nkv = DD * 2 * DD;
    cvtw_kernel<<<nq / 1024, 256>>>(Wq, pwq, nq);
    cvtw_kernel<<<nkv / 1024, 256>>>(Wkv, pwkv, nkv);
    cvtw_kernel<<<nq / 1024, 256>>>(Wp, pwp, nq);

    ada_kernel<<<BB, 256>>>(cond, W_ada, b_ada);
    ln_x_kernel<<<BB * VV, 128>>>(x);
    ln_ctx_kernel<<<BB * LL, 128>>>(context, g_ctx, b_ctx);

    dim3 gq(DD / 128, (BB * VV) / 128);
    gemm_mma_kernel<1, 0, 0><<<gq, 256>>>(ph, pwq, (const float*)0,
                                          (const float*)0, pq, BB * VV, DD, DD);
    dim3 gkv((2 * DD) / 128, (BB * LL) / 128);
    gemm_mma_kernel<1, 0, 0><<<gkv, 256>>>(pctxn, pwkv, (const float*)0,
                                           (const float*)0, pkv, BB * LL,
                                           2 * DD, DD);

    dim3 ga(VV / 64, BB * HH);
    attn_mma_kernel<<<ga, 256, ATTN_SMEM_BYTES>>>(cmask);

    dim3 go(DD / 128, (BB * VV) / 128);
    gemm_mma_kernel<0, 1, 1><<<go, 256>>>(pao, pwp, bp, x, out, BB * VV, DD, DD);
}

// round 6
// speedup vs baseline: 3.0302x; 1.1497x over previous
#include <cuda_runtime.h>
#include <cstdint>
#include <cstddef>

typedef unsigned short bf16;   // raw bf16 storage; no cuda_bf16.h needed

#define BB 8
#define VV 4096
#define LL 1024
#define DD 512
#define HH 8
#define HDIM 64

// ---------------- scratch (device globals; no allocations allowed) ----------
__device__ float g_params[BB * 2 * DD];
__device__ bf16  g_h[BB * VV * DD];
__device__ bf16  g_ctxn[BB * LL * DD];
__device__ bf16  g_q[BB * VV * DD];
__device__ bf16  g_kv[BB * LL * 2 * DD];
__device__ bf16  g_ao[BB * VV * DD];
__device__ bf16  g_wq[DD * DD];
__device__ bf16  g_wkv[DD * 2 * DD];
__device__ bf16  g_wp[DD * DD];

// ---------------- helpers ----------------------------------------------------
__device__ __forceinline__ unsigned pack2(float a, float b) {
    unsigned r;
    asm("cvt.rn.bf16x2.f32 %0, %1, %2;" : "=r"(r) : "f"(b), "f"(a));
    return r;
}
__device__ __forceinline__ uint32_t sptr(const void* p) {
    return (uint32_t)__cvta_generic_to_shared(p);
}
__device__ __forceinline__ void ldm_x4(uint32_t* r, uint32_t a) {
    asm volatile("ldmatrix.sync.aligned.m8n8.x4.shared.b16 {%0,%1,%2,%3}, [%4];"
                 : "=r"(r[0]), "=r"(r[1]), "=r"(r[2]), "=r"(r[3]) : "r"(a));
}
__device__ __forceinline__ void ldm_x4t(uint32_t* r, uint32_t a) {
    asm volatile("ldmatrix.sync.aligned.m8n8.x4.trans.shared.b16 {%0,%1,%2,%3}, [%4];"
                 : "=r"(r[0]), "=r"(r[1]), "=r"(r[2]), "=r"(r[3]) : "r"(a));
}
__device__ __forceinline__ void mma16816(float* d, const uint32_t* a,
                                         const uint32_t* b) {
    asm volatile(
        "mma.sync.aligned.m16n8k16.row.col.f32.bf16.bf16.f32 "
        "{%0,%1,%2,%3},{%4,%5,%6,%7},{%8,%9},{%0,%1,%2,%3};"
        : "+f"(d[0]), "+f"(d[1]), "+f"(d[2]), "+f"(d[3])
        : "r"(a[0]), "r"(a[1]), "r"(a[2]), "r"(a[3]), "r"(b[0]), "r"(b[1]));
}
__device__ __forceinline__ void cp16(void* smem, const void* gmem) {
    asm volatile("cp.async.cg.shared.global [%0], [%1], 16;"
                 :: "r"(sptr(smem)), "l"(gmem));
}
__device__ __forceinline__ void cp_commit() {
    asm volatile("cp.async.commit_group;");
}
__device__ __forceinline__ void cp_wait0() {
    asm volatile("cp.async.wait_group 0;");
}
__device__ __forceinline__ void cp_wait1() {
    asm volatile("cp.async.wait_group 1;");
}
// fast e^x for x <= 0 (FFMA/ALU only; avoids MUFU bottleneck)
__device__ __forceinline__ float fexp(float x) {
    float t = fmaxf(x * 1.44269504f, -126.f);
    int ti = __float2int_rn(t);
    float f = t - (float)ti;
    float p = 0.00961813f;
    p = p * f + 0.0555041f;
    p = p * f + 0.240227f;
    p = p * f + 0.693147f;
    p = p * f + 1.0f;
    return __int_as_float((ti + 127) << 23) * p;
}

// ---------------- weight fp32 -> bf16 ----------------------------------------
__global__ void __launch_bounds__(256) cvtw_kernel(const float* __restrict__ src,
                                                   bf16* __restrict__ dst, int n) {
    int i = (blockIdx.x * 256 + threadIdx.x) * 4;
    if (i < n) {
        float4 v = *(const float4*)(src + i);
        *(uint2*)(dst + i) = make_uint2(pack2(v.x, v.y), pack2(v.z, v.w));
    }
}

// ---------------- 1. silu(cond) @ W_ada + b_ada ------------------------------
// grid (16 col-chunks, 8 batches), 256 threads: 4 threads per column, K split.
__global__ void __launch_bounds__(256) ada_kernel(const float* __restrict__ cond,
                                                  const float* __restrict__ W,
                                                  const float* __restrict__ bias) {
    __shared__ float sc[DD];
    __shared__ float red[3][64];
    const int b = blockIdx.y;
    const int tid = threadIdx.x;
    for (int i = tid; i < DD; i += 256) {
        float c = cond[b * DD + i];
        sc[i] = c / (1.f + __expf(-c));
    }
    __syncthreads();
    const int jl = tid & 63;
    const int j = blockIdx.x * 64 + jl;
    const int ks = tid >> 6;              // 0..3, each covers 128 K
    const float* wp = W + (size_t)(ks * 128) * (2 * DD) + j;
    const float* scp = sc + ks * 128;
    float acc = 0.f;
    #pragma unroll 4
    for (int d = 0; d < 128; d++) acc += scp[d] * wp[(size_t)d * (2 * DD)];
    if (ks > 0) red[ks - 1][jl] = acc;
    __syncthreads();
    if (ks == 0) {
        acc += red[0][jl] + red[1][jl] + red[2][jl] + bias[j];
        g_params[b * 2 * DD + j] = acc;
    }
}

// ---------------- 2. LN(x)*(1+scale)+shift -> g_h (bf16) ---------------------
__global__ void __launch_bounds__(128) ln_x_kernel(const float* __restrict__ x) {
    const int row = blockIdx.x;
    const int b = row >> 12;
    const float* xr = x + (size_t)row * DD;
    float4 v = ((const float4*)xr)[threadIdx.x];
    float s = v.x + v.y + v.z + v.w;
    float sq = v.x * v.x + v.y * v.y + v.z * v.z + v.w * v.w;
    #pragma unroll
    for (int o = 16; o; o >>= 1) {
        s += __shfl_xor_sync(0xffffffffu, s, o);
        sq += __shfl_xor_sync(0xffffffffu, sq, o);
    }
    __shared__ float ss[4];
    __shared__ float ssq[4];
    const int w = threadIdx.x >> 5;
    if ((threadIdx.x & 31) == 0) { ss[w] = s; ssq[w] = sq; }
    __syncthreads();
    s = ss[0] + ss[1] + ss[2] + ss[3];
    sq = ssq[0] + ssq[1] + ssq[2] + ssq[3];
    const float mu = s * (1.f / DD);
    const float rstd = rsqrtf(sq * (1.f / DD) - mu * mu + 1e-5f);
    const int d0 = threadIdx.x * 4;
    const float* pr = g_params + b * 2 * DD;
    float o0 = (v.x - mu) * rstd * (1.f + pr[d0 + 0]) + pr[DD + d0 + 0];
    float o1 = (v.y - mu) * rstd * (1.f + pr[d0 + 1]) + pr[DD + d0 + 1];
    float o2 = (v.z - mu) * rstd * (1.f + pr[d0 + 2]) + pr[DD + d0 + 2];
    float o3 = (v.w - mu) * rstd * (1.f + pr[d0 + 3]) + pr[DD + d0 + 3];
    ((uint2*)(g_h + (size_t)row * DD))[threadIdx.x] =
        make_uint2(pack2(o0, o1), pack2(o2, o3));
}

// ---------------- 3. LN(context)*g+b -> g_ctxn (bf16) ------------------------
__global__ void __launch_bounds__(128) ln_ctx_kernel(const float* __restrict__ c,
                                                     const float* __restrict__ gam,
                                                     const float* __restrict__ bvec) {
    const int row = blockIdx.x;
    const float* xr = c + (size_t)row * DD;
    float4 v = ((const float4*)xr)[threadIdx.x];
    float s = v.x + v.y + v.z + v.w;
    float sq = v.x * v.x + v.y * v.y + v.z * v.z + v.w * v.w;
    #pragma unroll
    for (int o = 16; o; o >>= 1) {
        s += __shfl_xor_sync(0xffffffffu, s, o);
        sq += __shfl_xor_sync(0xffffffffu, sq, o);
    }
    __shared__ float ss[4];
    __shared__ float ssq[4];
    const int w = threadIdx.x >> 5;
    if ((threadIdx.x & 31) == 0) { ss[w] = s; ssq[w] = sq; }
    __syncthreads();
    s = ss[0] + ss[1] + ss[2] + ss[3];
    sq = ssq[0] + ssq[1] + ssq[2] + ssq[3];
    const float mu = s * (1.f / DD);
    const float rstd = rsqrtf(sq * (1.f / DD) - mu * mu + 1e-5f);
    const int d0 = threadIdx.x * 4;
    float o0 = (v.x - mu) * rstd * gam[d0 + 0] + bvec[d0 + 0];
    float o1 = (v.y - mu) * rstd * gam[d0 + 1] + bvec[d0 + 1];
    float o2 = (v.z - mu) * rstd * gam[d0 + 2] + bvec[d0 + 2];
    float o3 = (v.w - mu) * rstd * gam[d0 + 3] + bvec[d0 + 3];
    ((uint2*)(g_ctxn + (size_t)row * DD))[threadIdx.x] =
        make_uint2(pack2(o0, o1), pack2(o2, o3));
}

// ---------------- bf16 tensor-core GEMM with cp.async double buffer ----------
// CTA 128x128, BK=64, 8 warps (2x4), warp tile 64x32.
#define AS_SZ (128 * 72)
#define BS_SZ (64 * 136)
#define GEMM_SMEM ((2 * AS_SZ + 2 * BS_SZ) * 2)
template <int OUT_BF16, int BIAS, int RES>
__global__ void __launch_bounds__(256) gemm_mma_kernel(
    const bf16* __restrict__ A, const bf16* __restrict__ B,
    const float* __restrict__ bias, const float* __restrict__ res,
    void* __restrict__ Cv, int M, int N, int K) {
    extern __shared__ __align__(16) char gsm[];
    bf16* As = (bf16*)gsm;            // [2][128][72]
    bf16* Bs = As + 2 * AS_SZ;        // [2][64][136]
    const int tid = threadIdx.x;
    const int lane = tid & 31;
    const int warp = tid >> 5;
    const int wm = warp >> 2;
    const int wn = warp & 3;
    const int m0 = blockIdx.y * 128;
    const int n0 = blockIdx.x * 128;
    float acc[4][4][4] = {};

    const int ar = tid >> 1;                 // A: 256 threads -> 128 rows x 2
    const int ac = (tid & 1) * 32;           //    two 16B chunks per... (use loop)
    (void)ar; (void)ac;

    const int KT = K / 64;
    // tile loader: 128x64 A (4 iters), 64x128 B (4 iters), 16B each
    #define LOAD_TILE(k0, p)                                                   \
        do {                                                                   \
            _Pragma("unroll")                                                  \
            for (int i = 0; i < 4; i++) {                                      \
                int c = tid + i * 256;                                         \
                int r = c >> 3;                                                \
                int col = (c & 7) * 8;                                         \
                cp16(&As[(p) * AS_SZ + r * 72 + col],                          \
                     A + (size_t)(m0 + r) * K + (k0) + col);                   \
            }                                                                  \
            _Pragma("unroll")                                                  \
            for (int i = 0; i < 4; i++) {                                      \
                int c = tid + i * 256;                                         \
                int r = c >> 4;                                                \
                int col = (c & 15) * 8;                                        \
                cp16(&Bs[(p) * BS_SZ + r * 136 + col],                         \
                     B + (size_t)((k0) + r) * N + n0 + col);                   \
            }                                                                  \
            cp_commit();                                                       \
        } while (0)

    LOAD_TILE(0, 0);
    for (int kt = 0; kt < KT; kt++) {
        if (kt + 1 < KT) {
            LOAD_TILE((kt + 1) * 64, (kt + 1) & 1);
            cp_wait1();
        } else {
            cp_wait0();
        }
        __syncthreads();
        const int p = kt & 1;
        #pragma unroll
        for (int ks = 0; ks < 4; ks++) {
            uint32_t af[4][4];
            #pragma unroll
            for (int mi = 0; mi < 4; mi++) {
                ldm_x4(af[mi], sptr(&As[p * AS_SZ +
                                        (wm * 64 + mi * 16 + (lane & 15)) * 72 +
                                        ks * 16 + (lane >> 4) * 8]));
            }
            uint32_t bq[2][4];
            #pragma unroll
            for (int nj = 0; nj < 2; nj++) {
                ldm_x4t(bq[nj], sptr(&Bs[p * BS_SZ +
                                         (ks * 16 + (lane & 15)) * 136 +
                                         wn * 32 + nj * 16 + (lane >> 4) * 8]));
            }
            #pragma unroll
            for (int mi = 0; mi < 4; mi++) {
                #pragma unroll
                for (int ni = 0; ni < 4; ni++) {
                    uint32_t bb[2];
                    bb[0] = bq[ni >> 1][(ni & 1) * 2];
                    bb[1] = bq[ni >> 1][(ni & 1) * 2 + 1];
                    mma16816(acc[mi][ni], af[mi], bb);
                }
            }
        }
        __syncthreads();
    }
    #undef LOAD_TILE

    const int grp = lane >> 2;
    const int tig = lane & 3;
    #pragma unroll
    for (int mi = 0; mi < 4; mi++) {
        #pragma unroll
        for (int ni = 0; ni < 4; ni++) {
            const int row = m0 + wm * 64 + mi * 16 + grp;
            const int col = n0 + wn * 32 + ni * 8 + tig * 2;
            if (OUT_BF16) {
                bf16* C = (bf16*)Cv;
                *(unsigned*)&C[(size_t)row * N + col] =
                    pack2(acc[mi][ni][0], acc[mi][ni][1]);
                *(unsigned*)&C[(size_t)(row + 8) * N + col] =
                    pack2(acc[mi][ni][2], acc[mi][ni][3]);
            } else {
                float* C = (float*)Cv;
                float b0 = 0.f;
                float b1 = 0.f;
                if (BIAS) { b0 = bias[col]; b1 = bias[col + 1]; }
                float2 v0 = make_float2(acc[mi][ni][0] + b0, acc[mi][ni][1] + b1);
                float2 v1 = make_float2(acc[mi][ni][2] + b0, acc[mi][ni][3] + b1);
                if (RES) {
                    float2 r0 = *(const float2*)&res[(size_t)row * N + col];
                    float2 r1 = *(const float2*)&res[(size_t)(row + 8) * N + col];
                    v0.x += r0.x; v0.y += r0.y; v1.x += r1.x; v1.y += r1.y;
                }
                *(float2*)&C[(size_t)row * N + col] = v0;
                *(float2*)&C[(size_t)(row + 8) * N + col] = v1;
            }
        }
    }
}

// ---------------- flash attention, tensor cores ------------------------------
// CTA: one (b,h), 64 q rows; loop over L in chunks of 128. 8 warps.
#define ATTN_SMEM_BYTES 98560
__global__ void __launch_bounds__(256) attn_mma_kernel(const int* __restrict__ cmask) {
    extern __shared__ __align__(16) char sm_raw[];
    bf16* Qs = (bf16*)sm_raw;              // [64][72]
    bf16* Ks = Qs + 64 * 72;               // [128][72]
    bf16* Vs = Ks + 128 * 72;              // [128][72]
    bf16* Ps = Vs + 128 * 72;              // [64][136]
    float* Ss = (float*)(Ps + 64 * 136);   // [64][132]
    float* smax = Ss + 64 * 132;
    float* ssum = smax + 64;
    float* scorr = ssum + 64;
    int* smask = (int*)(scorr + 64);       // [128]

    const int bh = blockIdx.y;
    const int b = bh >> 3;
    const int h = bh & 7;
    const int q0 = blockIdx.x * 64;
    const int tid = threadIdx.x;
    const int lane = tid & 31;
    const int warp = tid >> 5;
    const int grp = lane >> 2;
    const int tig = lane & 3;
    const int wm = warp >> 2;
    const int wn = warp & 3;

    const bf16* qp = g_q + (size_t)(b * VV + q0) * DD + h * HDIM;
    #pragma unroll
    for (int i = 0; i < 2; i++) {
        int c = tid + i * 256;
        int r = c >> 3;
        int col = (c & 7) * 8;
        *(uint4*)&Qs[r * 72 + col] = *(const uint4*)(qp + (size_t)r * DD + col);
    }
    if (tid < 64) { smax[tid] = -1e30f; ssum[tid] = 0.f; }

    float opv[2][2][4] = {};

    for (int l0 = 0; l0 < LL; l0 += 128) {
        __syncthreads();
        const bf16* kp = g_kv + (size_t)(b * LL + l0) * (2 * DD) + h * HDIM;
        #pragma unroll
        for (int i = 0; i < 4; i++) {
            int c = tid + i * 256;
            int r = c >> 3;
            int col = (c & 7) * 8;
            *(uint4*)&Ks[r * 72 + col] =
                *(const uint4*)(kp + (size_t)r * (2 * DD) + col);
            *(uint4*)&Vs[r * 72 + col] =
                *(const uint4*)(kp + (size_t)r * (2 * DD) + DD + col);
        }
        if (tid < 128) smask[tid] = cmask[(size_t)b * LL + l0 + tid];
        __syncthreads();

        // ---- S = Q @ K^T : warp handles cols [warp*16, warp*16+16) ----
        float sacc[4][2][4] = {};
        #pragma unroll
        for (int ks = 0; ks < 4; ks++) {
            uint32_t af[4][4];
            #pragma unroll
            for (int mi = 0; mi < 4; mi++) {
                ldm_x4(af[mi], sptr(&Qs[(mi * 16 + (lane & 15)) * 72 +
                                        ks * 16 + (lane >> 4) * 8]));
            }
            uint32_t kf[4];
            ldm_x4(kf, sptr(&Ks[(warp * 16 + (lane & 15)) * 72 +
                                ks * 16 + (lane >> 4) * 8]));
            uint32_t b0[2];
            uint32_t b1[2];
            b0[0] = kf[0]; b0[1] = kf[2];
            b1[0] = kf[1]; b1[1] = kf[3];
            #pragma unroll
            for (int mi = 0; mi < 4; mi++) {
                mma16816(sacc[mi][0], af[mi], b0);
                mma16816(sacc[mi][1], af[mi], b1);
            }
        }
        #pragma unroll
        for (int mi = 0; mi < 4; mi++) {
            #pragma unroll
            for (int ni = 0; ni < 2; ni++) {
                int r = mi * 16 + grp;
                int cc = warp * 16 + ni * 8 + tig * 2;
                *(float2*)&Ss[r * 132 + cc] =
                    make_float2(sacc[mi][ni][0], sacc[mi][ni][1]);
                *(float2*)&Ss[(r + 8) * 132 + cc] =
                    make_float2(sacc[mi][ni][2], sacc[mi][ni][3]);
            }
        }
        __syncthreads();

        // ---- softmax: 4 threads per row, 32 cols each ----
        {
            const int r = tid >> 2;
            const int p = tid & 3;
            const float* srow = Ss + r * 132 + p * 32;
            const int* mrow = smask + p * 32;
            float mx = -1e30f;
            #pragma unroll
            for (int j = 0; j < 32; j++) {
                float sv = mrow[j] ? srow[j] * 0.125f : -1e30f;
                mx = fmaxf(mx, sv);
            }
            mx = fmaxf(mx, __shfl_xor_sync(0xffffffffu, mx, 1));
            mx = fmaxf(mx, __shfl_xor_sync(0xffffffffu, mx, 2));
            float mold = smax[r];
            float mnew = fmaxf(mold, mx);
            float sum = 0.f;
            bf16* prow = Ps + r * 136 + p * 32;
            #pragma unroll
            for (int j = 0; j < 32; j += 2) {
                float sv0 = mrow[j] ? srow[j] * 0.125f : -1e30f;
                float sv1 = mrow[j + 1] ? srow[j + 1] * 0.125f : -1e30f;
                float e0 = fexp(sv0 - mnew);
                float e1 = fexp(sv1 - mnew);
                sum += e0 + e1;
                *(unsigned*)&prow[j] = pack2(e0, e1);
            }
            sum += __shfl_xor_sync(0xffffffffu, sum, 1);
            sum += __shfl_xor_sync(0xffffffffu, sum, 2);
            if (p == 0) {
                float corr = fexp(mold - mnew);
                smax[r] = mnew;
                ssum[r] = ssum[r] * corr + sum;
                scorr[r] = corr;
            }
        }
        __syncthreads();

        // ---- O = O*corr + P @ V : warp tile 32x16 ----
        #pragma unroll
        for (int mi = 0; mi < 2; mi++) {
            float c0 = scorr[wm * 32 + mi * 16 + grp];
            float c1 = scorr[wm * 32 + mi * 16 + 8 + grp];
            #pragma unroll
            for (int ni = 0; ni < 2; ni++) {
                opv[mi][ni][0] *= c0; opv[mi][ni][1] *= c0;
                opv[mi][ni][2] *= c1; opv[mi][ni][3] *= c1;
            }
        }
        #pragma unroll
        for (int ks = 0; ks < 8; ks++) {
            uint32_t af[2][4];
            #pragma unroll
            for (int mi = 0; mi < 2; mi++) {
                ldm_x4(af[mi], sptr(&Ps[(wm * 32 + mi * 16 + (lane & 15)) * 136 +
                                        ks * 16 + (lane >> 4) * 8]));
            }
            uint32_t vf[4];
            ldm_x4t(vf, sptr(&Vs[(ks * 16 + (lane & 15)) * 72 +
                                 wn * 16 + (lane >> 4) * 8]));
            uint32_t b0[2];
            uint32_t b1[2];
            b0[0] = vf[0]; b0[1] = vf[1];
            b1[0] = vf[2]; b1[1] = vf[3];
            #pragma unroll
            for (int mi = 0; mi < 2; mi++) {
                mma16816(opv[mi][0], af[mi], b0);
                mma16816(opv[mi][1], af[mi], b1);
            }
        }
    }
    __syncthreads();

    bf16* op = g_ao + (size_t)(b * VV + q0) * DD + h * HDIM;
    #pragma unroll
    for (int mi = 0; mi < 2; mi++) {
        int r0 = wm * 32 + mi * 16 + grp;
        float inv0 = 1.f / ssum[r0];
        float inv1 = 1.f / ssum[r0 + 8];
        #pragma unroll
        for (int ni = 0; ni < 2; ni++) {
            int cc = wn * 16 + ni * 8 + tig * 2;
            *(unsigned*)&op[(size_t)r0 * DD + cc] =
                pack2(opv[mi][ni][0] * inv0, opv[mi][ni][1] * inv0);
            *(unsigned*)&op[(size_t)(r0 + 8) * DD + cc] =
                pack2(opv[mi][ni][2] * inv1, opv[mi][ni][3] * inv1);
        }
    }
}

// ---------------- launch ------------------------------------------------------
extern "C" void kernel_launch(void* const* d_in, const int* in_sizes, int n_in,
                              void* d_out, int out_size) {
    const float* x       = (const float*)d_in[0];
    const float* context = (const float*)d_in[1];
    const float* cond    = (const float*)d_in[2];
    const int*   cmask   = (const int*)d_in[3];
    const float* W_ada   = (const float*)d_in[4];
    const float* b_ada   = (const float*)d_in[5];
    const float* g_ctx   = (const float*)d_in[6];
    const float* b_ctx   = (const float*)d_in[7];
    const float* Wq      = (const float*)d_in[8];
    const float* Wkv     = (const float*)d_in[9];
    const float* Wp      = (const float*)d_in[10];
    const float* bp      = (const float*)d_in[11];
    float* out = (float*)d_out;

    bf16* ph;
    bf16* pctxn;
    bf16* pq;
    bf16* pkv;
    bf16* pao;
    bf16* pwq;
    bf16* pwkv;
    bf16* pwp;
    cudaGetSymbolAddress((void**)&ph, g_h);
    cudaGetSymbolAddress((void**)&pctxn, g_ctxn);
    cudaGetSymbolAddress((void**)&pq, g_q);
    cudaGetSymbolAddress((void**)&pkv, g_kv);
    cudaGetSymbolAddress((void**)&pao, g_ao);
    cudaGetSymbolAddress((void**)&pwq, g_wq);
    cudaGetSymbolAddress((void**)&pwkv, g_wkv);
    cudaGetSymbolAddress((void**)&pwp, g_wp);

    cudaFuncSetAttribute(attn_mma_kernel,
                         cudaFuncAttributeMaxDynamicSharedMemorySize,
                         ATTN_SMEM_BYTES);
    cudaFuncSetAttribute(gemm_mma_kernel<1, 0, 0>,
                         cudaFuncAttributeMaxDynamicSharedMemorySize,
                         GEMM_SMEM);
    cudaFuncSetAttribute(gemm_mma_kernel<0, 1, 1>,
                         cudaFuncAttributeMaxDynamicSharedMemorySize,
                         GEMM_SMEM);

    int nq = DD * DD;
    int nkv = DD * 2 * DD;
    cvtw_kernel<<<nq / 1024, 256>>>(Wq, pwq, nq);
    cvtw_kernel<<<nkv / 1024, 256>>>(Wkv, pwkv, nkv);
    cvtw_kernel<<<nq / 1024, 256>>>(Wp, pwp, nq);

    ada_kernel<<<dim3(16, BB), 256>>>(cond, W_ada, b_ada);
    ln_x_kernel<<<BB * VV, 128>>>(x);
    ln_ctx_kernel<<<BB * LL, 128>>>(context, g_ctx, b_ctx);

    dim3 gq(DD / 128, (BB * VV) / 128);
    gemm_mma_kernel<1, 0, 0><<<gq, 256, GEMM_SMEM>>>(
        ph, pwq, (const float*)0, (const float*)0, pq, BB * VV, DD, DD);
    dim3 gkv((2 * DD) / 128, (BB * LL) / 128);
    gemm_mma_kernel<1, 0, 0><<<gkv, 256, GEMM_SMEM>>>(
        pctxn, pwkv, (const float*)0, (const float*)0, pkv, BB * LL, 2 * DD, DD);

    dim3 ga(VV / 64, BB * HH);
    attn_mma_kernel<<<ga, 256, ATTN_SMEM_BYTES>>>(cmask);

    dim3 go(DD / 128, (BB * VV) / 128);
    gemm_mma_kernel<0, 1, 1><<<go, 256, GEMM_SMEM>>>(
        pao, pwp, bp, x, out, BB * VV, DD, DD);
}

// round 8
// speedup vs baseline: 5.6522x; 1.8653x over previous
#include <cuda_runtime.h>
#include <cstdint>
#include <cstddef>

typedef unsigned short bf16;   // raw bf16 storage; no cuda_bf16.h needed

#define BB 8
#define VV 4096
#define LL 1024
#define DD 512
#define HH 8
#define HDIM 64

// ---------------- scratch (device globals; no allocations allowed) ----------
__device__ float g_params[BB * 2 * DD];
__device__ bf16  g_h[BB * VV * DD];
__device__ bf16  g_ctxn[BB * LL * DD];
__device__ bf16  g_q[BB * VV * DD];
__device__ bf16  g_kv[BB * LL * 2 * DD];
__device__ bf16  g_ao[BB * VV * DD];
__device__ bf16  g_wq[DD * DD];
__device__ bf16  g_wkv[DD * 2 * DD];
__device__ bf16  g_wp[DD * DD];

// ---------------- helpers ----------------------------------------------------
__device__ __forceinline__ unsigned pack2(float a, float b) {
    unsigned r;
    asm("cvt.rn.bf16x2.f32 %0, %1, %2;" : "=r"(r) : "f"(b), "f"(a));
    return r;
}
__device__ __forceinline__ uint32_t sptr(const void* p) {
    return (uint32_t)__cvta_generic_to_shared(p);
}
__device__ __forceinline__ void ldm_x4(uint32_t* r, uint32_t a) {
    asm volatile("ldmatrix.sync.aligned.m8n8.x4.shared.b16 {%0,%1,%2,%3}, [%4];"
                 : "=r"(r[0]), "=r"(r[1]), "=r"(r[2]), "=r"(r[3]) : "r"(a));
}
__device__ __forceinline__ void ldm_x4t(uint32_t* r, uint32_t a) {
    asm volatile("ldmatrix.sync.aligned.m8n8.x4.trans.shared.b16 {%0,%1,%2,%3}, [%4];"
                 : "=r"(r[0]), "=r"(r[1]), "=r"(r[2]), "=r"(r[3]) : "r"(a));
}
__device__ __forceinline__ void mma16816(float* d, const uint32_t* a,
                                         const uint32_t* b) {
    asm volatile(
        "mma.sync.aligned.m16n8k16.row.col.f32.bf16.bf16.f32 "
        "{%0,%1,%2,%3},{%4,%5,%6,%7},{%8,%9},{%0,%1,%2,%3};"
        : "+f"(d[0]), "+f"(d[1]), "+f"(d[2]), "+f"(d[3])
        : "r"(a[0]), "r"(a[1]), "r"(a[2]), "r"(a[3]), "r"(b[0]), "r"(b[1]));
}
__device__ __forceinline__ void cp16(void* smem, const void* gmem) {
    asm volatile("cp.async.cg.shared.global [%0], [%1], 16;"
                 :: "r"(sptr(smem)), "l"(gmem));
}
__device__ __forceinline__ void cp_commit() {
    asm volatile("cp.async.commit_group;");
}
__device__ __forceinline__ void cp_wait0() {
    asm volatile("cp.async.wait_group 0;");
}
__device__ __forceinline__ void cp_wait1() {
    asm volatile("cp.async.wait_group 1;");
}
// fast e^x for x <= 0 (FFMA/ALU only; avoids MUFU bottleneck)
__device__ __forceinline__ float fexp(float x) {
    float t = fmaxf(x * 1.44269504f, -126.f);
    int ti = __float2int_rn(t);
    float f = t - (float)ti;
    float p = 0.00961813f;
    p = p * f + 0.0555041f;
    p = p * f + 0.240227f;
    p = p * f + 0.693147f;
    p = p * f + 1.0f;
    return __int_as_float((ti + 127) << 23) * p;
}

// ---------------- weight fp32 -> bf16 ----------------------------------------
__global__ void __launch_bounds__(256) cvtw_kernel(const float* __restrict__ src,
                                                   bf16* __restrict__ dst, int n) {
    int i = (blockIdx.x * 256 + threadIdx.x) * 4;
    if (i < n) {
        float4 v = *(const float4*)(src + i);
        *(uint2*)(dst + i) = make_uint2(pack2(v.x, v.y), pack2(v.z, v.w));
    }
}

// ---------------- 1. silu(cond) @ W_ada + b_ada ------------------------------
__global__ void __launch_bounds__(256) ada_kernel(const float* __restrict__ cond,
                                                  const float* __restrict__ W,
                                                  const float* __restrict__ bias) {
    __shared__ float sc[DD];
    __shared__ float red[3][64];
    const int b = blockIdx.y;
    const int tid = threadIdx.x;
    for (int i = tid; i < DD; i += 256) {
        float c = cond[b * DD + i];
        sc[i] = c / (1.f + __expf(-c));
    }
    __syncthreads();
    const int jl = tid & 63;
    const int j = blockIdx.x * 64 + jl;
    const int ks = tid >> 6;              // 0..3, each covers 128 K
    const float* wp = W + (size_t)(ks * 128) * (2 * DD) + j;
    const float* scp = sc + ks * 128;
    float acc = 0.f;
    #pragma unroll 4
    for (int d = 0; d < 128; d++) acc += scp[d] * wp[(size_t)d * (2 * DD)];
    if (ks > 0) red[ks - 1][jl] = acc;
    __syncthreads();
    if (ks == 0) {
        acc += red[0][jl] + red[1][jl] + red[2][jl] + bias[j];
        g_params[b * 2 * DD + j] = acc;
    }
}

// ---------------- 2. LN(x)*(1+scale)+shift -> g_h (bf16) ---------------------
__global__ void __launch_bounds__(128) ln_x_kernel(const float* __restrict__ x) {
    const int row = blockIdx.x;
    const int b = row >> 12;
    const float* xr = x + (size_t)row * DD;
    float4 v = ((const float4*)xr)[threadIdx.x];
    float s = v.x + v.y + v.z + v.w;
    float sq = v.x * v.x + v.y * v.y + v.z * v.z + v.w * v.w;
    #pragma unroll
    for (int o = 16; o; o >>= 1) {
        s += __shfl_xor_sync(0xffffffffu, s, o);
        sq += __shfl_xor_sync(0xffffffffu, sq, o);
    }
    __shared__ float ss[4];
    __shared__ float ssq[4];
    const int w = threadIdx.x >> 5;
    if ((threadIdx.x & 31) == 0) { ss[w] = s; ssq[w] = sq; }
    __syncthreads();
    s = ss[0] + ss[1] + ss[2] + ss[3];
    sq = ssq[0] + ssq[1] + ssq[2] + ssq[3];
    const float mu = s * (1.f / DD);
    const float rstd = rsqrtf(sq * (1.f / DD) - mu * mu + 1e-5f);
    const int d0 = threadIdx.x * 4;
    const float* pr = g_params + b * 2 * DD;
    float o0 = (v.x - mu) * rstd * (1.f + pr[d0 + 0]) + pr[DD + d0 + 0];
    float o1 = (v.y - mu) * rstd * (1.f + pr[d0 + 1]) + pr[DD + d0 + 1];
    float o2 = (v.z - mu) * rstd * (1.f + pr[d0 + 2]) + pr[DD + d0 + 2];
    float o3 = (v.w - mu) * rstd * (1.f + pr[d0 + 3]) + pr[DD + d0 + 3];
    ((uint2*)(g_h + (size_t)row * DD))[threadIdx.x] =
        make_uint2(pack2(o0, o1), pack2(o2, o3));
}

// ---------------- 3. LN(context)*g+b -> g_ctxn (bf16) ------------------------
__global__ void __launch_bounds__(128) ln_ctx_kernel(const float* __restrict__ c,
                                                     const float* __restrict__ gam,
                                                     const float* __restrict__ bvec) {
    const int row = blockIdx.x;
    const float* xr = c + (size_t)row * DD;
    float4 v = ((const float4*)xr)[threadIdx.x];
    float s = v.x + v.y + v.z + v.w;
    float sq = v.x * v.x + v.y * v.y + v.z * v.z + v.w * v.w;
    #pragma unroll
    for (int o = 16; o; o >>= 1) {
        s += __shfl_xor_sync(0xffffffffu, s, o);
        sq += __shfl_xor_sync(0xffffffffu, sq, o);
    }
    __shared__ float ss[4];
    __shared__ float ssq[4];
    const int w = threadIdx.x >> 5;
    if ((threadIdx.x & 31) == 0) { ss[w] = s; ssq[w] = sq; }
    __syncthreads();
    s = ss[0] + ss[1] + ss[2] + ss[3];
    sq = ssq[0] + ssq[1] + ssq[2] + ssq[3];
    const float mu = s * (1.f / DD);
    const float rstd = rsqrtf(sq * (1.f / DD) - mu * mu + 1e-5f);
    const int d0 = threadIdx.x * 4;
    float o0 = (v.x - mu) * rstd * gam[d0 + 0] + bvec[d0 + 0];
    float o1 = (v.y - mu) * rstd * gam[d0 + 1] + bvec[d0 + 1];
    float o2 = (v.z - mu) * rstd * gam[d0 + 2] + bvec[d0 + 2];
    float o3 = (v.w - mu) * rstd * gam[d0 + 3] + bvec[d0 + 3];
    ((uint2*)(g_ctxn + (size_t)row * DD))[threadIdx.x] =
        make_uint2(pack2(o0, o1), pack2(o2, o3));
}

// ---------------- bf16 tensor-core GEMM with cp.async double buffer ----------
#define AS_SZ (128 * 72)
#define BS_SZ (64 * 136)
#define GEMM_SMEM ((2 * AS_SZ + 2 * BS_SZ) * 2)
template <int OUT_BF16, int BIAS, int RES>
__global__ void __launch_bounds__(256) gemm_mma_kernel(
    const bf16* __restrict__ A, const bf16* __restrict__ B,
    const float* __restrict__ bias, const float* __restrict__ res,
    void* __restrict__ Cv, int M, int N, int K) {
    extern __shared__ __align__(16) char gsm[];
    bf16* As = (bf16*)gsm;            // [2][128][72]
    bf16* Bs = As + 2 * AS_SZ;        // [2][64][136]
    const int tid = threadIdx.x;
    const int lane = tid & 31;
    const int warp = tid >> 5;
    const int wm = warp >> 2;
    const int wn = warp & 3;
    const int m0 = blockIdx.y * 128;
    const int n0 = blockIdx.x * 128;
    float acc[4][4][4] = {};

    const int KT = K / 64;
    #define LOAD_TILE(k0, p)                                                   \
        do {                                                                   \
            _Pragma("unroll")                                                  \
            for (int i = 0; i < 4; i++) {                                      \
                int c = tid + i * 256;                                         \
                int r = c >> 3;                                                \
                int col = (c & 7) * 8;                                         \
                cp16(&As[(p) * AS_SZ + r * 72 + col],                          \
                     A + (size_t)(m0 + r) * K + (k0) + col);                   \
            }                                                                  \
            _Pragma("unroll")                                                  \
            for (int i = 0; i < 4; i++) {                                      \
                int c = tid + i * 256;                                         \
                int r = c >> 4;                                                \
                int col = (c & 15) * 8;                                        \
                cp16(&Bs[(p) * BS_SZ + r * 136 + col],                         \
                     B + (size_t)((k0) + r) * N + n0 + col);                   \
            }                                                                  \
            cp_commit();                                                       \
        } while (0)

    LOAD_TILE(0, 0);
    for (int kt = 0; kt < KT; kt++) {
        if (kt + 1 < KT) {
            LOAD_TILE((kt + 1) * 64, (kt + 1) & 1);
            cp_wait1();
        } else {
            cp_wait0();
        }
        __syncthreads();
        const int p = kt & 1;
        #pragma unroll
        for (int ks = 0; ks < 4; ks++) {
            uint32_t af[4][4];
            #pragma unroll
            for (int mi = 0; mi < 4; mi++) {
                ldm_x4(af[mi], sptr(&As[p * AS_SZ +
                                        (wm * 64 + mi * 16 + (lane & 15)) * 72 +
                                        ks * 16 + (lane >> 4) * 8]));
            }
            uint32_t bq[2][4];
            #pragma unroll
            for (int nj = 0; nj < 2; nj++) {
                ldm_x4t(bq[nj], sptr(&Bs[p * BS_SZ +
                                         (ks * 16 + (lane & 15)) * 136 +
                                         wn * 32 + nj * 16 + (lane >> 4) * 8]));
            }
            #pragma unroll
            for (int mi = 0; mi < 4; mi++) {
                #pragma unroll
                for (int ni = 0; ni < 4; ni++) {
                    uint32_t bb[2];
                    bb[0] = bq[ni >> 1][(ni & 1) * 2];
                    bb[1] = bq[ni >> 1][(ni & 1) * 2 + 1];
                    mma16816(acc[mi][ni], af[mi], bb);
                }
            }
        }
        __syncthreads();
    }
    #undef LOAD_TILE

    const int grp = lane >> 2;
    const int tig = lane & 3;
    #pragma unroll
    for (int mi = 0; mi < 4; mi++) {
        #pragma unroll
        for (int ni = 0; ni < 4; ni++) {
            const int row = m0 + wm * 64 + mi * 16 + grp;
            const int col = n0 + wn * 32 + ni * 8 + tig * 2;
            if (OUT_BF16) {
                bf16* C = (bf16*)Cv;
                *(unsigned*)&C[(size_t)row * N + col] =
                    pack2(acc[mi][ni][0], acc[mi][ni][1]);
                *(unsigned*)&C[(size_t)(row + 8) * N + col] =
                    pack2(acc[mi][ni][2], acc[mi][ni][3]);
            } else {
                float* C = (float*)Cv;
                float b0 = 0.f;
                float b1 = 0.f;
                if (BIAS) { b0 = bias[col]; b1 = bias[col + 1]; }
                float2 v0 = make_float2(acc[mi][ni][0] + b0, acc[mi][ni][1] + b1);
                float2 v1 = make_float2(acc[mi][ni][2] + b0, acc[mi][ni][3] + b1);
                if (RES) {
                    float2 r0 = *(const float2*)&res[(size_t)row * N + col];
                    float2 r1 = *(const float2*)&res[(size_t)(row + 8) * N + col];
                    v0.x += r0.x; v0.y += r0.y; v1.x += r1.x; v1.y += r1.y;
                }
                *(float2*)&C[(size_t)row * N + col] = v0;
                *(float2*)&C[(size_t)(row + 8) * N + col] = v1;
            }
        }
    }
}

// ---------------- flash attention, register-resident softmax -----------------
// CTA: one (b,h), 128 q rows; 8 warps, each warp owns 16 full q rows.
// smem bytes: Q 2*KSZ, K 2 bufs * 2*KSZ, V 2 bufs * 2*KSZ, mask 1KB = 10*KSZ+1KB
#define KSZ (128 * 72)
#define ATTN_SMEM_BYTES (10 * KSZ + 2 * 128 * 4)
__global__ void __launch_bounds__(256) attn_mma_kernel(const int* __restrict__ cmask) {
    extern __shared__ __align__(16) char sm_raw[];
    bf16* Qs = (bf16*)sm_raw;            // [128][72]
    bf16* Ks = Qs + KSZ;                 // [2][128][72]
    bf16* Vs = Ks + 2 * KSZ;             // [2][128][72]
    int* smask = (int*)(Vs + 2 * KSZ);   // [2][128]

    const int bh = blockIdx.y;
    const int b = bh >> 3;
    const int h = bh & 7;
    const int q0 = blockIdx.x * 128;
    const int tid = threadIdx.x;
    const int lane = tid & 31;
    const int warp = tid >> 5;
    const int grp = lane >> 2;
    const int tig = lane & 3;

    // load Q tile (128 x 64)
    const bf16* qp = g_q + (size_t)(b * VV + q0) * DD + h * HDIM;
    #pragma unroll
    for (int i = 0; i < 4; i++) {
        int c = tid + i * 256;
        int r = c >> 3;
        int col = (c & 7) * 8;
        *(uint4*)&Qs[r * 72 + col] = *(const uint4*)(qp + (size_t)r * DD + col);
    }
    __syncthreads();

    // Q fragments (warp rows warp*16..+15), reused for all chunks
    uint32_t aq[4][4];
    #pragma unroll
    for (int ks = 0; ks < 4; ks++) {
        ldm_x4(aq[ks], sptr(&Qs[(warp * 16 + (lane & 15)) * 72 +
                                ks * 16 + (lane >> 4) * 8]));
    }

    float mrow0 = -1e30f, mrow1 = -1e30f;
    float lrow0 = 0.f, lrow1 = 0.f;
    float opv[8][4] = {};

    #define LOADKV(l0, p)                                                      \
        do {                                                                   \
            const bf16* kp = g_kv + (size_t)(b * LL + (l0)) * (2 * DD) +       \
                             h * HDIM;                                         \
            _Pragma("unroll")                                                  \
            for (int i = 0; i < 4; i++) {                                      \
                int c = tid + i * 256;                                         \
                int r = c >> 3;                                                \
                int col = (c & 7) * 8;                                         \
                cp16(&Ks[(p) * KSZ + r * 72 + col],                            \
                     kp + (size_t)r * (2 * DD) + col);                         \
                cp16(&Vs[(p) * KSZ + r * 72 + col],                            \
                     kp + (size_t)r * (2 * DD) + DD + col);                    \
            }                                                                  \
            if (tid < 32)                                                      \
                cp16(&smask[(p) * 128 + tid * 4],                              \
                     cmask + (size_t)b * LL + (l0) + tid * 4);                 \
            cp_commit();                                                       \
        } while (0)

    LOADKV(0, 0);
    for (int kt = 0; kt < 8; kt++) {
        const int p = kt & 1;
        if (kt < 7) {
            LOADKV((kt + 1) * 128, p ^ 1);
            cp_wait1();
        } else {
            cp_wait0();
        }
        __syncthreads();   // buf p ready; prior compute on p done last iter

        // ---- S = Q @ K^T : full 16 x 128 stripe per warp ----
        float sacc[16][4];
        #pragma unroll
        for (int nb = 0; nb < 16; nb++) {
            sacc[nb][0] = 0.f; sacc[nb][1] = 0.f;
            sacc[nb][2] = 0.f; sacc[nb][3] = 0.f;
        }
        #pragma unroll
        for (int ks = 0; ks < 4; ks++) {
            #pragma unroll
            for (int nb16 = 0; nb16 < 8; nb16++) {
                uint32_t kf[4];
                ldm_x4(kf, sptr(&Ks[p * KSZ +
                                    (nb16 * 16 + (lane & 15)) * 72 +
                                    ks * 16 + (lane >> 4) * 8]));
                uint32_t b0[2];
                uint32_t b1[2];
                b0[0] = kf[0]; b0[1] = kf[2];
                b1[0] = kf[1]; b1[1] = kf[3];
                mma16816(sacc[nb16 * 2], aq[ks], b0);
                mma16816(sacc[nb16 * 2 + 1], aq[ks], b1);
            }
        }

        // ---- mask + scale + row max (in registers) ----
        float mx0 = -1e30f, mx1 = -1e30f;
        #pragma unroll
        for (int nb = 0; nb < 16; nb++) {
            int2 mv = *(const int2*)&smask[p * 128 + nb * 8 + tig * 2];
            sacc[nb][0] = mv.x ? sacc[nb][0] * 0.125f : -1e30f;
            sacc[nb][1] = mv.y ? sacc[nb][1] * 0.125f : -1e30f;
            sacc[nb][2] = mv.x ? sacc[nb][2] * 0.125f : -1e30f;
            sacc[nb][3] = mv.y ? sacc[nb][3] * 0.125f : -1e30f;
            mx0 = fmaxf(mx0, fmaxf(sacc[nb][0], sacc[nb][1]));
            mx1 = fmaxf(mx1, fmaxf(sacc[nb][2], sacc[nb][3]));
        }
        mx0 = fmaxf(mx0, __shfl_xor_sync(0xffffffffu, mx0, 1));
        mx0 = fmaxf(mx0, __shfl_xor_sync(0xffffffffu, mx0, 2));
        mx1 = fmaxf(mx1, __shfl_xor_sync(0xffffffffu, mx1, 1));
        mx1 = fmaxf(mx1, __shfl_xor_sync(0xffffffffu, mx1, 2));
        float mnew0 = fmaxf(mrow0, mx0);
        float mnew1 = fmaxf(mrow1, mx1);
        float corr0 = fexp(mrow0 - mnew0);
        float corr1 = fexp(mrow1 - mnew1);
        mrow0 = mnew0;
        mrow1 = mnew1;

        // ---- exp in registers + row sums ----
        float sum0 = 0.f, sum1 = 0.f;
        #pragma unroll
        for (int nb = 0; nb < 16; nb++) {
            sacc[nb][0] = fexp(sacc[nb][0] - mnew0);
            sacc[nb][1] = fexp(sacc[nb][1] - mnew0);
            sacc[nb][2] = fexp(sacc[nb][2] - mnew1);
            sacc[nb][3] = fexp(sacc[nb][3] - mnew1);
            sum0 += sacc[nb][0] + sacc[nb][1];
            sum1 += sacc[nb][2] + sacc[nb][3];
        }
        sum0 += __shfl_xor_sync(0xffffffffu, sum0, 1);
        sum0 += __shfl_xor_sync(0xffffffffu, sum0, 2);
        sum1 += __shfl_xor_sync(0xffffffffu, sum1, 1);
        sum1 += __shfl_xor_sync(0xffffffffu, sum1, 2);
        lrow0 = lrow0 * corr0 + sum0;
        lrow1 = lrow1 * corr1 + sum1;

        // ---- rescale O, then O += P @ V (P packed from sacc regs) ----
        #pragma unroll
        for (int nb = 0; nb < 8; nb++) {
            opv[nb][0] *= corr0; opv[nb][1] *= corr0;
            opv[nb][2] *= corr1; opv[nb][3] *= corr1;
        }
        #pragma unroll
        for (int ks8 = 0; ks8 < 8; ks8++) {
            uint32_t af[4];
            af[0] = pack2(sacc[2 * ks8][0], sacc[2 * ks8][1]);
            af[1] = pack2(sacc[2 * ks8][2], sacc[2 * ks8][3]);
            af[2] = pack2(sacc[2 * ks8 + 1][0], sacc[2 * ks8 + 1][1]);
            af[3] = pack2(sacc[2 * ks8 + 1][2], sacc[2 * ks8 + 1][3]);
            #pragma unroll
            for (int nv = 0; nv < 4; nv++) {
                uint32_t vf[4];
                ldm_x4t(vf, sptr(&Vs[p * KSZ +
                                     (ks8 * 16 + (lane & 15)) * 72 +
                                     nv * 16 + (lane >> 4) * 8]));
                uint32_t b0[2];
                uint32_t b1[2];
                b0[0] = vf[0]; b0[1] = vf[1];
                b1[0] = vf[2]; b1[1] = vf[3];
                mma16816(opv[nv * 2], af, b0);
                mma16816(opv[nv * 2 + 1], af, b1);
            }
        }
        __syncthreads();   // done with buf p before it is refilled
    }
    #undef LOADKV

    // ---- epilogue: normalize + store ----
    const float inv0 = 1.f / lrow0;
    const float inv1 = 1.f / lrow1;
    bf16* op = g_ao + (size_t)(b * VV + q0 + warp * 16 + grp) * DD + h * HDIM;
    #pragma unroll
    for (int nb = 0; nb < 8; nb++) {
        int col = nb * 8 + tig * 2;
        *(unsigned*)&op[col] = pack2(opv[nb][0] * inv0, opv[nb][1] * inv0);
        *(unsigned*)&op[(size_t)8 * DD + col] =
            pack2(opv[nb][2] * inv1, opv[nb][3] * inv1);
    }
}

// ---------------- launch ------------------------------------------------------
extern "C" void kernel_launch(void* const* d_in, const int* in_sizes, int n_in,
                              void* d_out, int out_size) {
    const float* x       = (const float*)d_in[0];
    const float* context = (const float*)d_in[1];
    const float* cond    = (const float*)d_in[2];
    const int*   cmask   = (const int*)d_in[3];
    const float* W_ada   = (const float*)d_in[4];
    const float* b_ada   = (const float*)d_in[5];
    const float* g_ctx   = (const float*)d_in[6];
    const float* b_ctx   = (const float*)d_in[7];
    const float* Wq      = (const float*)d_in[8];
    const float* Wkv     = (const float*)d_in[9];
    const float* Wp      = (const float*)d_in[10];
    const float* bp      = (const float*)d_in[11];
    float* out = (float*)d_out;

    bf16* ph;
    bf16* pctxn;
    bf16* pq;
    bf16* pkv;
    bf16* pao;
    bf16* pwq;
    bf16* pwkv;
    bf16* pwp;
    cudaGetSymbolAddress((void**)&ph, g_h);
    cudaGetSymbolAddress((void**)&pctxn, g_ctxn);
    cudaGetSymbolAddress((void**)&pq, g_q);
    cudaGetSymbolAddress((void**)&pkv, g_kv);
    cudaGetSymbolAddress((void**)&pao, g_ao);
    cudaGetSymbolAddress((void**)&pwq, g_wq);
    cudaGetSymbolAddress((void**)&pwkv, g_wkv);
    cudaGetSymbolAddress((void**)&pwp, g_wp);

    cudaFuncSetAttribute(attn_mma_kernel,
                         cudaFuncAttributeMaxDynamicSharedMemorySize,
                         ATTN_SMEM_BYTES);
    cudaFuncSetAttribute(gemm_mma_kernel<1, 0, 0>,
                         cudaFuncAttributeMaxDynamicSharedMemorySize,
                         GEMM_SMEM);
    cudaFuncSetAttribute(gemm_mma_kernel<0, 1, 1>,
                         cudaFuncAttributeMaxDynamicSharedMemorySize,
                         GEMM_SMEM);

    int nq = DD * DD;
    int nkv = DD * 2 * DD;
    cvtw_kernel<<<nq / 1024, 256>>>(Wq, pwq, nq);
    cvtw_kernel<<<nkv / 1024, 256>>>(Wkv, pwkv, nkv);
    cvtw_kernel<<<nq / 1024, 256>>>(Wp, pwp, nq);

    ada_kernel<<<dim3(16, BB), 256>>>(cond, W_ada, b_ada);
    ln_x_kernel<<<BB * VV, 128>>>(x);
    ln_ctx_kernel<<<BB * LL, 128>>>(context, g_ctx, b_ctx);

    dim3 gq(DD / 128, (BB * VV) / 128);
    gemm_mma_kernel<1, 0, 0><<<gq, 256, GEMM_SMEM>>>(
        ph, pwq, (const float*)0, (const float*)0, pq, BB * VV, DD, DD);
    dim3 gkv((2 * DD) / 128, (BB * LL) / 128);
    gemm_mma_kernel<1, 0, 0><<<gkv, 256, GEMM_SMEM>>>(
        pctxn, pwkv, (const float*)0, (const float*)0, pkv, BB * LL, 2 * DD, DD);

    dim3 ga(VV / 128, BB * HH);
    attn_mma_kernel<<<ga, 256, ATTN_SMEM_BYTES>>>(cmask);

    dim3 go(DD / 128, (BB * VV) / 128);
    gemm_mma_kernel<0, 1, 1><<<go, 256, GEMM_SMEM>>>(
        pao, pwp, bp, x, out, BB * VV, DD, DD);
}